// round 14
// baseline (speedup 1.0000x reference)
#include <cuda_runtime.h>
#include <cuda_bf16.h>
#include <cstdint>

// ---------------------------------------------------------------------------
// SupGCL_GConv: 3x [GEMM(64x64)+bias+relu] interleaved with 2x high-pass
// graph filter:  out = z*(1-inv) - (sum_{j->i} z[j])*inv,  inv = 1/(deg*cnt)
//
// R14:
//  - FFMA2 GEMM rebalanced for occupancy: 256 thr/block, 4 rows x 8 cols per
//    thread (R13's 128thr/8x8 halved occupancy to 16% and went latency-bound).
//  - Filter gather source compressed to bf16: GEMM epilogue (stages 0,1) also
//    writes a bf16 copy of the row; neighbor gathers read 128B/row instead of
//    256B (halves the filter's dominant L2 traffic). Node's own row and the
//    filter output stay fp32, so bf16 noise only enters via sum*inv (~0.07 of
//    the output) -> ~1.4e-4 rel, 7x under the 1e-3 gate.
// ---------------------------------------------------------------------------

#define N_NODES 100000
#define D 64
#define N_EDGES 1200000
#define NBMAX 512     // >= ceil(N_NODES/256) = 391
#define GR 128        // gemm rows per block
#define XPAD 4        // xs row padding (floats)

__device__ __align__(16) float g_zA[(size_t)N_NODES * D];   // gemm1 out (fp32)
__device__ __align__(16) float g_zB[(size_t)N_NODES * D];   // gemm2 out (fp32)
__device__ __align__(16) float g_zf[(size_t)N_NODES * D];   // filtered z
__device__ __align__(16) __nv_bfloat16 g_zh[(size_t)N_NODES * D]; // bf16 copy
__device__ int g_csrc[N_EDGES];     // CSC: src id per dst-sorted slot
__device__ int g_rowptr[N_NODES];   // CSC row starts
__device__ int g_cur[N_NODES];      // bucket cursors
__device__ int g_deg[N_NODES];      // outdeg+1
__device__ int g_cnt[N_NODES];      // indeg+1
__device__ int g_part[NBMAX];       // scan partials
__device__ int g_is64;

// ---------------------------------------------------------------------------
__global__ void detect_dtype_kernel(const long long* __restrict__ ei) {
    // int64 buffer -> first 8 values are valid node ids; int32 viewed as int64
    // packs two ids -> >= 2^32 w.h.p.
    if (blockIdx.x == 0 && threadIdx.x == 0) {
        bool ok = true;
        for (int i = 0; i < 8; i++) {
            long long v = ei[i];
            if (v < 0 || v >= N_NODES) ok = false;
        }
        g_is64 = ok ? 1 : 0;
    }
}

__global__ void init_counts_kernel(int n) {
    int i = blockIdx.x * blockDim.x + threadIdx.x;
    if (i < n) { g_deg[i] = 1; g_cnt[i] = 1; }   // self loops
}

// Count degrees only (no edge materialization).
__global__ void edge_prep_kernel(const void* __restrict__ ei, int E, int n) {
    int e = blockIdx.x * blockDim.x + threadIdx.x;
    if (e >= E) return;
    int s, t;
    if (g_is64) {
        s = (int)((const long long*)ei)[e];
        t = (int)((const long long*)ei)[E + e];
    } else {
        s = ((const int*)ei)[e];
        t = ((const int*)ei)[E + e];
    }
    if ((unsigned)s >= (unsigned)n) s = 0;   // defensive: wrong beats crash
    if ((unsigned)t >= (unsigned)n) t = 0;
    atomicAdd(&g_deg[s], 1);
    atomicAdd(&g_cnt[t], 1);
}

// ---- parallel exclusive scan of indeg (= cnt-1) -> rowptr, cur ------------
__global__ void scan_partial_kernel(int n) {
    __shared__ int sh[256];
    int i = blockIdx.x * 256 + threadIdx.x;
    sh[threadIdx.x] = (i < n) ? (g_cnt[i] - 1) : 0;
    __syncthreads();
#pragma unroll
    for (int d = 128; d > 0; d >>= 1) {
        if (threadIdx.x < d) sh[threadIdx.x] += sh[threadIdx.x + d];
        __syncthreads();
    }
    if (threadIdx.x == 0) g_part[blockIdx.x] = sh[0];
}

__global__ void scan_bases_kernel(int nb) {
    __shared__ int sh[NBMAX];
    int tid = threadIdx.x;
    int v = (tid < nb) ? g_part[tid] : 0;
    sh[tid] = v;
    __syncthreads();
    for (int d = 1; d < NBMAX; d <<= 1) {
        int u = (tid >= d) ? sh[tid - d] : 0;
        __syncthreads();
        sh[tid] += u;
        __syncthreads();
    }
    if (tid < nb) g_part[tid] = sh[tid] - v;   // exclusive base per block
}

__global__ void scan_fill_kernel(int n) {
    __shared__ int sh[256];
    int tid = threadIdx.x;
    int i = blockIdx.x * 256 + tid;
    int v = (i < n) ? (g_cnt[i] - 1) : 0;
    sh[tid] = v;
    __syncthreads();
    for (int d = 1; d < 256; d <<= 1) {
        int u = (tid >= d) ? sh[tid - d] : 0;
        __syncthreads();
        sh[tid] += u;
        __syncthreads();
    }
    if (i < n) {
        int off = g_part[blockIdx.x] + sh[tid] - v;   // exclusive
        g_rowptr[i] = off;
        g_cur[i]    = off;
    }
}

// Bucket edges by dst into CSC (re-decodes indices from the input buffer).
__global__ void bucket_kernel(const void* __restrict__ ei, int E, int n) {
    int e = blockIdx.x * blockDim.x + threadIdx.x;
    if (e >= E) return;
    int s, t;
    if (g_is64) {
        s = (int)((const long long*)ei)[e];
        t = (int)((const long long*)ei)[E + e];
    } else {
        s = ((const int*)ei)[e];
        t = ((const int*)ei)[E + e];
    }
    if ((unsigned)s >= (unsigned)n) s = 0;
    if ((unsigned)t >= (unsigned)n) t = 0;
    int pos = atomicAdd(&g_cur[t], 1);
    g_csrc[pos] = s;
}

// Atomic-free pull filter: 16 lanes per dst node, lane q covers cols
// 4q..4q+3. Neighbor rows gathered from the bf16 copy (8B per lane instead
// of 16B); own row read fp32; fp32 accumulate; fp32 output.
// sel: 0 -> own row from g_zA, 1 -> from g_zB.  Writes g_zf.
__global__ __launch_bounds__(256)
void filter_kernel(int n, int sel) {
    int t = blockIdx.x * blockDim.x + threadIdx.x;
    int node = t >> 4;
    int q    = t & 15;
    if (node >= n) return;
    const float* z = sel ? g_zB : g_zA;

    int start = g_rowptr[node];
    int cnt   = g_cnt[node];          // indeg+1
    int end   = start + cnt - 1;

    float4 s0 = make_float4(0.f, 0.f, 0.f, 0.f);
    float4 s1 = make_float4(0.f, 0.f, 0.f, 0.f);
    float4 s2 = make_float4(0.f, 0.f, 0.f, 0.f);
    float4 s3 = make_float4(0.f, 0.f, 0.f, 0.f);
    int j = start;
    for (; j + 3 < end; j += 4) {
        int a0 = __ldg(&g_csrc[j]);
        int a1 = __ldg(&g_csrc[j + 1]);
        int a2 = __ldg(&g_csrc[j + 2]);
        int a3 = __ldg(&g_csrc[j + 3]);
        uint2 u0 = *reinterpret_cast<const uint2*>(g_zh + (size_t)a0 * D + q * 4);
        uint2 u1 = *reinterpret_cast<const uint2*>(g_zh + (size_t)a1 * D + q * 4);
        uint2 u2 = *reinterpret_cast<const uint2*>(g_zh + (size_t)a2 * D + q * 4);
        uint2 u3 = *reinterpret_cast<const uint2*>(g_zh + (size_t)a3 * D + q * 4);
        float2 f;
        f = __bfloat1622float2(*reinterpret_cast<const __nv_bfloat162*>(&u0.x));
        s0.x += f.x; s0.y += f.y;
        f = __bfloat1622float2(*reinterpret_cast<const __nv_bfloat162*>(&u0.y));
        s0.z += f.x; s0.w += f.y;
        f = __bfloat1622float2(*reinterpret_cast<const __nv_bfloat162*>(&u1.x));
        s1.x += f.x; s1.y += f.y;
        f = __bfloat1622float2(*reinterpret_cast<const __nv_bfloat162*>(&u1.y));
        s1.z += f.x; s1.w += f.y;
        f = __bfloat1622float2(*reinterpret_cast<const __nv_bfloat162*>(&u2.x));
        s2.x += f.x; s2.y += f.y;
        f = __bfloat1622float2(*reinterpret_cast<const __nv_bfloat162*>(&u2.y));
        s2.z += f.x; s2.w += f.y;
        f = __bfloat1622float2(*reinterpret_cast<const __nv_bfloat162*>(&u3.x));
        s3.x += f.x; s3.y += f.y;
        f = __bfloat1622float2(*reinterpret_cast<const __nv_bfloat162*>(&u3.y));
        s3.z += f.x; s3.w += f.y;
    }
    for (; j < end; j++) {
        int a = __ldg(&g_csrc[j]);
        uint2 u = *reinterpret_cast<const uint2*>(g_zh + (size_t)a * D + q * 4);
        float2 f;
        f = __bfloat1622float2(*reinterpret_cast<const __nv_bfloat162*>(&u.x));
        s0.x += f.x; s0.y += f.y;
        f = __bfloat1622float2(*reinterpret_cast<const __nv_bfloat162*>(&u.y));
        s0.z += f.x; s0.w += f.y;
    }
    float4 sum;
    sum.x = (s0.x + s1.x) + (s2.x + s3.x);
    sum.y = (s0.y + s1.y) + (s2.y + s3.y);
    sum.z = (s0.z + s1.z) + (s2.z + s3.z);
    sum.w = (s0.w + s1.w) + (s2.w + s3.w);

    float inv = 1.0f / ((float)g_deg[node] * (float)cnt);
    float om  = 1.0f - inv;
    float4 zv = *reinterpret_cast<const float4*>(z + (size_t)node * D + q * 4);
    float4 o;
    o.x = zv.x * om - sum.x * inv;
    o.y = zv.y * om - sum.y * inv;
    o.z = zv.z * om - sum.z * inv;
    o.w = zv.w * om - sum.w * inv;
    *reinterpret_cast<float4*>(g_zf + (size_t)node * D + q * 4) = o;
}

// ---------------------------------------------------------------------------
// FFMA2 GEMM: out = relu(X @ W + b)
// stage 0: X = Xext, out = g_zA (+bf16 g_zh)
// stage 1: X = g_zf, out = g_zB (+bf16 g_zh)
// stage 2: X = g_zf, out = Oext (no bf16 copy)
// 256 threads/block, 128-row tile. Thread (cg = tid&7, rw = tid>>3):
//   cols 8*cg..8*cg+7 (4 f32x2 pairs), rows rw + 32*r, r = 0..3.
// ---------------------------------------------------------------------------
__global__ __launch_bounds__(256)
void gemm_relu_kernel(const float* __restrict__ Xext,
                      float* __restrict__ Oext,
                      const float* __restrict__ W,
                      const float* __restrict__ B,
                      int n, int stage) {
    __shared__ float Ws[D * D];
    __shared__ float xs[GR * (D + XPAD)];
    const int tid = threadIdx.x;
    const int r0  = blockIdx.x * GR;
    const int XS  = D + XPAD;

    const float* X   = (stage == 0) ? Xext : g_zf;
    float*       out = (stage == 0) ? g_zA : (stage == 1 ? g_zB : Oext);

    // load W (4096 floats = 1024 float4), 4 per thread
    {
        const float4* Wv  = reinterpret_cast<const float4*>(W);
        float4*       Wsv = reinterpret_cast<float4*>(Ws);
#pragma unroll
        for (int i = 0; i < 4; i++) Wsv[tid + 256 * i] = Wv[tid + 256 * i];
    }
    // load 128x64 x tile (2048 float4), 8 per thread
#pragma unroll
    for (int i = 0; i < 8; i++) {
        int idx  = tid + 256 * i;
        int row  = idx >> 4;
        int qc   = idx & 15;
        int grow = r0 + row;
        float4 v = make_float4(0.f, 0.f, 0.f, 0.f);
        if (grow < n)
            v = *reinterpret_cast<const float4*>(X + (size_t)grow * D + qc * 4);
        *reinterpret_cast<float4*>(xs + row * XS + qc * 4) = v;
    }
    __syncthreads();

    const int cg = tid & 7;    // col group: cols 8*cg .. 8*cg+7
    const int rw = tid >> 3;   // row base: rows rw + 32*r, r = 0..3

    // accumulators = packed f32x2 pairs, pre-loaded with bias
    unsigned long long acc[4][4];
    {
        const double2* bv = reinterpret_cast<const double2*>(B + cg * 8);
        double2 ba = bv[0], bb = bv[1];
        unsigned long long bp0 = __double_as_longlong(ba.x);
        unsigned long long bp1 = __double_as_longlong(ba.y);
        unsigned long long bp2 = __double_as_longlong(bb.x);
        unsigned long long bp3 = __double_as_longlong(bb.y);
#pragma unroll
        for (int r = 0; r < 4; r++) {
            acc[r][0] = bp0; acc[r][1] = bp1; acc[r][2] = bp2; acc[r][3] = bp3;
        }
    }

#pragma unroll 4
    for (int k0 = 0; k0 < D; k0 += 4) {
        float4 xr[4];
#pragma unroll
        for (int r = 0; r < 4; r++)
            xr[r] = *reinterpret_cast<const float4*>(&xs[(rw + 32 * r) * XS + k0]);
#pragma unroll
        for (int kk = 0; kk < 4; kk++) {
            const double2* wp =
                reinterpret_cast<const double2*>(&Ws[(k0 + kk) * D + cg * 8]);
            double2 wa = wp[0], wb = wp[1];
            unsigned long long w0 = __double_as_longlong(wa.x);
            unsigned long long w1 = __double_as_longlong(wa.y);
            unsigned long long w2 = __double_as_longlong(wb.x);
            unsigned long long w3 = __double_as_longlong(wb.y);
#pragma unroll
            for (int r = 0; r < 4; r++) {
                float xv = (kk == 0) ? xr[r].x : (kk == 1) ? xr[r].y
                         : (kk == 2) ? xr[r].z : xr[r].w;
                unsigned long long xx;
                asm("mov.b64 %0, {%1, %1};" : "=l"(xx) : "f"(xv));
                asm("fma.rn.f32x2 %0, %1, %2, %0;" : "+l"(acc[r][0]) : "l"(xx), "l"(w0));
                asm("fma.rn.f32x2 %0, %1, %2, %0;" : "+l"(acc[r][1]) : "l"(xx), "l"(w1));
                asm("fma.rn.f32x2 %0, %1, %2, %0;" : "+l"(acc[r][2]) : "l"(xx), "l"(w2));
                asm("fma.rn.f32x2 %0, %1, %2, %0;" : "+l"(acc[r][3]) : "l"(xx), "l"(w3));
            }
        }
    }

    // epilogue: unpack, relu, store fp32 (+bf16 copy for stages 0,1)
#pragma unroll
    for (int r = 0; r < 4; r++) {
        int grow = r0 + rw + 32 * r;
        if (grow < n) {
            float lo[4], hi[4];
#pragma unroll
            for (int c = 0; c < 4; c++)
                asm("mov.b64 {%0, %1}, %2;" : "=f"(lo[c]), "=f"(hi[c]) : "l"(acc[r][c]));
            float4 o1, o2;
            o1.x = fmaxf(lo[0], 0.f); o1.y = fmaxf(hi[0], 0.f);
            o1.z = fmaxf(lo[1], 0.f); o1.w = fmaxf(hi[1], 0.f);
            o2.x = fmaxf(lo[2], 0.f); o2.y = fmaxf(hi[2], 0.f);
            o2.z = fmaxf(lo[3], 0.f); o2.w = fmaxf(hi[3], 0.f);
            float* p = out + (size_t)grow * D + cg * 8;
            *reinterpret_cast<float4*>(p)     = o1;
            *reinterpret_cast<float4*>(p + 4) = o2;
            if (stage != 2) {
                __nv_bfloat162 h0 = __floats2bfloat162_rn(o1.x, o1.y);
                __nv_bfloat162 h1 = __floats2bfloat162_rn(o1.z, o1.w);
                __nv_bfloat162 h2 = __floats2bfloat162_rn(o2.x, o2.y);
                __nv_bfloat162 h3 = __floats2bfloat162_rn(o2.z, o2.w);
                uint4 hb;
                hb.x = *reinterpret_cast<unsigned*>(&h0);
                hb.y = *reinterpret_cast<unsigned*>(&h1);
                hb.z = *reinterpret_cast<unsigned*>(&h2);
                hb.w = *reinterpret_cast<unsigned*>(&h3);
                *reinterpret_cast<uint4*>(g_zh + (size_t)grow * D + cg * 8) = hb;
            }
        }
    }
}

// ---------------------------------------------------------------------------
extern "C" void kernel_launch(void* const* d_in, const int* in_sizes, int n_in,
                              void* d_out, int out_size) {
    // Bind inputs by element count (robust to ordering), positional fallback.
    int ix = -1, ie = -1, iW[3] = {-1, -1, -1}, ib[3] = {-1, -1, -1};
    int nW = 0, nb = 0;
    for (int i = 0; i < n_in; i++) {
        int s = in_sizes[i];
        if (s == N_NODES * D)          ix = i;
        else if (s == 2 * N_EDGES)     ie = i;
        else if (s == D * D && nW < 3) iW[nW++] = i;
        else if (s == D && nb < 3)     ib[nb++] = i;
    }
    if (ix < 0 || ie < 0 || nW < 3 || nb < 3) {
        ix = 0; ie = 1;
        iW[0] = 2; ib[0] = 3; iW[1] = 4; ib[1] = 5; iW[2] = 6; ib[2] = 7;
    }

    const float* x  = (const float*)d_in[ix];
    const void*  ei = d_in[ie];
    const float* W1 = (const float*)d_in[iW[0]];
    const float* b1 = (const float*)d_in[ib[0]];
    const float* W2 = (const float*)d_in[iW[1]];
    const float* b2 = (const float*)d_in[ib[1]];
    const float* W3 = (const float*)d_in[iW[2]];
    const float* b3 = (const float*)d_in[ib[2]];
    float* out = (float*)d_out;

    const int n = in_sizes[ix] / D;      // 100000
    const int E = in_sizes[ie] / 2;      // 1200000

    const int gemm_blocks   = (n + GR - 1) / GR;
    const int filter_blocks = (n * 16 + 255) / 256;
    const int node_blocks   = (n + 255) / 256;   // = NB for the scan

    // graph prep: dtype probe, degree counts
    detect_dtype_kernel<<<1, 32>>>((const long long*)ei);
    init_counts_kernel<<<node_blocks, 256>>>(n);
    edge_prep_kernel<<<(E + 255) / 256, 256>>>(ei, E, n);

    // layer 1: x -> g_zA (+ bf16 copy)
    gemm_relu_kernel<<<gemm_blocks, 256>>>(x, nullptr, W1, b1, n, 0);

    // CSC build: parallel scan + bucket
    scan_partial_kernel<<<node_blocks, 256>>>(n);
    scan_bases_kernel<<<1, NBMAX>>>(node_blocks);
    scan_fill_kernel<<<node_blocks, 256>>>(n);
    bucket_kernel<<<(E + 255) / 256, 256>>>(ei, E, n);

    // filter 1: bf16 gather + fp32 own-row -> g_zf
    filter_kernel<<<filter_blocks, 256>>>(n, 0);

    // layer 2: g_zf -> g_zB (+ bf16 copy)
    gemm_relu_kernel<<<gemm_blocks, 256>>>(nullptr, nullptr, W2, b2, n, 1);

    // filter 2
    filter_kernel<<<filter_blocks, 256>>>(n, 1);

    // layer 3: g_zf -> d_out
    gemm_relu_kernel<<<gemm_blocks, 256>>>(nullptr, out, W3, b3, n, 2);
}

// round 16
// speedup vs baseline: 1.1591x; 1.1591x over previous
#include <cuda_runtime.h>
#include <cuda_bf16.h>
#include <cstdint>

// ---------------------------------------------------------------------------
// SupGCL_GConv: 3x [GEMM(64x64)+bias+relu] interleaved with 2x high-pass
// graph filter:  out = z*(1-inv) - (sum_{j->i} z[j])*inv,  inv = 1/(deg*cnt)
//
// R16: FFMA2 GEMM with 48KB *static* smem (no cudaFuncSetAttribute — the two
// infra failures correlate with non-launch runtime APIs in kernel_launch).
//  - xs stored transposed (k-major, stride 128): adjacent rows form native
//    f32x2 pairs loaded pre-packed via LDS.128.
//  - W plain fp32 in smem; {w,w} packed with 4 mov.b64 per k (15% inst tax
//    instead of a 16KB smem tax; keeps 4 blocks/SM).
//  - 8 rows x 4 cols per thread, 256 thr, 128-row tile.
// Filter/prep: R14's measured-good bf16-gather pull filter + parallel scan.
// ---------------------------------------------------------------------------

#define N_NODES 100000
#define D 64
#define N_EDGES 1200000
#define NBMAX 512     // >= ceil(N_NODES/256) = 391
#define GR 128        // gemm rows per block
#define XSR 128       // transposed xs row stride (floats)

typedef unsigned long long ull;

__device__ __align__(16) float g_zA[(size_t)N_NODES * D];   // gemm1 out (fp32)
__device__ __align__(16) float g_zB[(size_t)N_NODES * D];   // gemm2 out (fp32)
__device__ __align__(16) float g_zf[(size_t)N_NODES * D];   // filtered z
__device__ __align__(16) __nv_bfloat16 g_zh[(size_t)N_NODES * D]; // bf16 copy
__device__ int g_csrc[N_EDGES];     // CSC: src id per dst-sorted slot
__device__ int g_rowptr[N_NODES];   // CSC row starts
__device__ int g_cur[N_NODES];      // bucket cursors
__device__ int g_deg[N_NODES];      // outdeg+1
__device__ int g_cnt[N_NODES];      // indeg+1
__device__ int g_part[NBMAX];       // scan partials
__device__ int g_is64;

// ---------------------------------------------------------------------------
__global__ void detect_dtype_kernel(const long long* __restrict__ ei) {
    if (blockIdx.x == 0 && threadIdx.x == 0) {
        bool ok = true;
        for (int i = 0; i < 8; i++) {
            long long v = ei[i];
            if (v < 0 || v >= N_NODES) ok = false;
        }
        g_is64 = ok ? 1 : 0;
    }
}

__global__ void init_counts_kernel(int n) {
    int i = blockIdx.x * blockDim.x + threadIdx.x;
    if (i < n) { g_deg[i] = 1; g_cnt[i] = 1; }   // self loops
}

__global__ void edge_prep_kernel(const void* __restrict__ ei, int E, int n) {
    int e = blockIdx.x * blockDim.x + threadIdx.x;
    if (e >= E) return;
    int s, t;
    if (g_is64) {
        s = (int)((const long long*)ei)[e];
        t = (int)((const long long*)ei)[E + e];
    } else {
        s = ((const int*)ei)[e];
        t = ((const int*)ei)[E + e];
    }
    if ((unsigned)s >= (unsigned)n) s = 0;
    if ((unsigned)t >= (unsigned)n) t = 0;
    atomicAdd(&g_deg[s], 1);
    atomicAdd(&g_cnt[t], 1);
}

// ---- parallel exclusive scan of indeg (= cnt-1) -> rowptr, cur ------------
__global__ void scan_partial_kernel(int n) {
    __shared__ int sh[256];
    int i = blockIdx.x * 256 + threadIdx.x;
    sh[threadIdx.x] = (i < n) ? (g_cnt[i] - 1) : 0;
    __syncthreads();
#pragma unroll
    for (int d = 128; d > 0; d >>= 1) {
        if (threadIdx.x < d) sh[threadIdx.x] += sh[threadIdx.x + d];
        __syncthreads();
    }
    if (threadIdx.x == 0) g_part[blockIdx.x] = sh[0];
}

__global__ void scan_bases_kernel(int nb) {
    __shared__ int sh[NBMAX];
    int tid = threadIdx.x;
    int v = (tid < nb) ? g_part[tid] : 0;
    sh[tid] = v;
    __syncthreads();
    for (int d = 1; d < NBMAX; d <<= 1) {
        int u = (tid >= d) ? sh[tid - d] : 0;
        __syncthreads();
        sh[tid] += u;
        __syncthreads();
    }
    if (tid < nb) g_part[tid] = sh[tid] - v;   // exclusive base per block
}

__global__ void scan_fill_kernel(int n) {
    __shared__ int sh[256];
    int tid = threadIdx.x;
    int i = blockIdx.x * 256 + tid;
    int v = (i < n) ? (g_cnt[i] - 1) : 0;
    sh[tid] = v;
    __syncthreads();
    for (int d = 1; d < 256; d <<= 1) {
        int u = (tid >= d) ? sh[tid - d] : 0;
        __syncthreads();
        sh[tid] += u;
        __syncthreads();
    }
    if (i < n) {
        int off = g_part[blockIdx.x] + sh[tid] - v;   // exclusive
        g_rowptr[i] = off;
        g_cur[i]    = off;
    }
}

__global__ void bucket_kernel(const void* __restrict__ ei, int E, int n) {
    int e = blockIdx.x * blockDim.x + threadIdx.x;
    if (e >= E) return;
    int s, t;
    if (g_is64) {
        s = (int)((const long long*)ei)[e];
        t = (int)((const long long*)ei)[E + e];
    } else {
        s = ((const int*)ei)[e];
        t = ((const int*)ei)[E + e];
    }
    if ((unsigned)s >= (unsigned)n) s = 0;
    if ((unsigned)t >= (unsigned)n) t = 0;
    int pos = atomicAdd(&g_cur[t], 1);
    g_csrc[pos] = s;
}

// Atomic-free pull filter: 16 lanes per dst node; neighbor rows gathered
// from the bf16 copy; own row fp32; fp32 accumulate; fp32 output.
__global__ __launch_bounds__(256)
void filter_kernel(int n, int sel) {
    int t = blockIdx.x * blockDim.x + threadIdx.x;
    int node = t >> 4;
    int q    = t & 15;
    if (node >= n) return;
    const float* z = sel ? g_zB : g_zA;

    int start = g_rowptr[node];
    int cnt   = g_cnt[node];          // indeg+1
    int end   = start + cnt - 1;

    float4 s0 = make_float4(0.f, 0.f, 0.f, 0.f);
    float4 s1 = make_float4(0.f, 0.f, 0.f, 0.f);
    float4 s2 = make_float4(0.f, 0.f, 0.f, 0.f);
    float4 s3 = make_float4(0.f, 0.f, 0.f, 0.f);
    int j = start;
    for (; j + 3 < end; j += 4) {
        int a0 = __ldg(&g_csrc[j]);
        int a1 = __ldg(&g_csrc[j + 1]);
        int a2 = __ldg(&g_csrc[j + 2]);
        int a3 = __ldg(&g_csrc[j + 3]);
        uint2 u0 = *reinterpret_cast<const uint2*>(g_zh + (size_t)a0 * D + q * 4);
        uint2 u1 = *reinterpret_cast<const uint2*>(g_zh + (size_t)a1 * D + q * 4);
        uint2 u2 = *reinterpret_cast<const uint2*>(g_zh + (size_t)a2 * D + q * 4);
        uint2 u3 = *reinterpret_cast<const uint2*>(g_zh + (size_t)a3 * D + q * 4);
        float2 f;
        f = __bfloat1622float2(*reinterpret_cast<const __nv_bfloat162*>(&u0.x));
        s0.x += f.x; s0.y += f.y;
        f = __bfloat1622float2(*reinterpret_cast<const __nv_bfloat162*>(&u0.y));
        s0.z += f.x; s0.w += f.y;
        f = __bfloat1622float2(*reinterpret_cast<const __nv_bfloat162*>(&u1.x));
        s1.x += f.x; s1.y += f.y;
        f = __bfloat1622float2(*reinterpret_cast<const __nv_bfloat162*>(&u1.y));
        s1.z += f.x; s1.w += f.y;
        f = __bfloat1622float2(*reinterpret_cast<const __nv_bfloat162*>(&u2.x));
        s2.x += f.x; s2.y += f.y;
        f = __bfloat1622float2(*reinterpret_cast<const __nv_bfloat162*>(&u2.y));
        s2.z += f.x; s2.w += f.y;
        f = __bfloat1622float2(*reinterpret_cast<const __nv_bfloat162*>(&u3.x));
        s3.x += f.x; s3.y += f.y;
        f = __bfloat1622float2(*reinterpret_cast<const __nv_bfloat162*>(&u3.y));
        s3.z += f.x; s3.w += f.y;
    }
    for (; j < end; j++) {
        int a = __ldg(&g_csrc[j]);
        uint2 u = *reinterpret_cast<const uint2*>(g_zh + (size_t)a * D + q * 4);
        float2 f;
        f = __bfloat1622float2(*reinterpret_cast<const __nv_bfloat162*>(&u.x));
        s0.x += f.x; s0.y += f.y;
        f = __bfloat1622float2(*reinterpret_cast<const __nv_bfloat162*>(&u.y));
        s0.z += f.x; s0.w += f.y;
    }
    float4 sum;
    sum.x = (s0.x + s1.x) + (s2.x + s3.x);
    sum.y = (s0.y + s1.y) + (s2.y + s3.y);
    sum.z = (s0.z + s1.z) + (s2.z + s3.z);
    sum.w = (s0.w + s1.w) + (s2.w + s3.w);

    float inv = 1.0f / ((float)g_deg[node] * (float)cnt);
    float om  = 1.0f - inv;
    float4 zv = *reinterpret_cast<const float4*>(z + (size_t)node * D + q * 4);
    float4 o;
    o.x = zv.x * om - sum.x * inv;
    o.y = zv.y * om - sum.y * inv;
    o.z = zv.z * om - sum.z * inv;
    o.w = zv.w * om - sum.w * inv;
    *reinterpret_cast<float4*>(g_zf + (size_t)node * D + q * 4) = o;
}

// ---------------------------------------------------------------------------
// FFMA2 GEMM, 48KB static smem: Ws fp32 [64][64] (16KB), xs transposed
// [k][row] stride 128 (32KB). Thread (cg = tid&15, rg = tid>>4): cols
// 4cg..4cg+3, rows 8rg..8rg+7 as 4 f32x2 row-pairs. Inner loop per k:
// 2x LDS.128 (x pairs) + 1x LDS.128 (w float4) + 4 mov.b64 + 16 FFMA2.
// stage 0: X=Xext,out=g_zA(+bf16)  1: X=g_zf,out=g_zB(+bf16)  2: X=g_zf,out=Oext
// ---------------------------------------------------------------------------
__global__ __launch_bounds__(256)
void gemm_relu_kernel(const float* __restrict__ Xext,
                      float* __restrict__ Oext,
                      const float* __restrict__ W,
                      const float* __restrict__ B,
                      int n, int stage) {
    __shared__ float Ws[D * D];          // 16KB
    __shared__ float xs[D * XSR];        // 32KB
    const int tid = threadIdx.x;
    const int r0  = blockIdx.x * GR;

    const float* X   = (stage == 0) ? Xext : g_zf;
    float*       out = (stage == 0) ? g_zA : (stage == 1 ? g_zB : Oext);

    // load W (1024 float4), 4 per thread
    {
        const float4* Wv  = reinterpret_cast<const float4*>(W);
        float4*       Wsv = reinterpret_cast<float4*>(Ws);
#pragma unroll
        for (int i = 0; i < 4; i++) Wsv[tid + 256 * i] = Wv[tid + 256 * i];
    }

    // build transposed x tile: xs[k*XSR + row] (conflict-free: lane -> row)
    {
        int rloc  = tid & 127;            // local row; lanes consecutive rows
        int qbase = tid >> 7;             // 0 or 1
        int grow  = r0 + rloc;
#pragma unroll
        for (int i = 0; i < 8; i++) {
            int qc = qbase + 2 * i;       // 16B quad index 0..15
            float4 v = make_float4(0.f, 0.f, 0.f, 0.f);
            if (grow < n)
                v = *reinterpret_cast<const float4*>(X + (size_t)grow * D + qc * 4);
            xs[(qc * 4 + 0) * XSR + rloc] = v.x;
            xs[(qc * 4 + 1) * XSR + rloc] = v.y;
            xs[(qc * 4 + 2) * XSR + rloc] = v.z;
            xs[(qc * 4 + 3) * XSR + rloc] = v.w;
        }
    }
    __syncthreads();

    const int cg = tid & 15;    // col group: cols 4cg..4cg+3
    const int rg = tid >> 4;    // rows 8rg..8rg+7

    // acc[m][c]: f32x2 pair = rows {8rg+2m, 8rg+2m+1}, col 4cg+c; init = bias
    ull acc[4][4];
    {
        float4 bv = *reinterpret_cast<const float4*>(B + cg * 4);
        ull b0, b1, b2, b3;
        asm("mov.b64 %0, {%1, %1};" : "=l"(b0) : "f"(bv.x));
        asm("mov.b64 %0, {%1, %1};" : "=l"(b1) : "f"(bv.y));
        asm("mov.b64 %0, {%1, %1};" : "=l"(b2) : "f"(bv.z));
        asm("mov.b64 %0, {%1, %1};" : "=l"(b3) : "f"(bv.w));
#pragma unroll
        for (int m = 0; m < 4; m++) {
            acc[m][0] = b0; acc[m][1] = b1; acc[m][2] = b2; acc[m][3] = b3;
        }
    }

    const float* xp = xs + 8 * rg;
    const float* wq = Ws + cg * 4;

#pragma unroll 8
    for (int k = 0; k < D; k++) {
        ulonglong2 xa = *reinterpret_cast<const ulonglong2*>(xp + k * XSR);
        ulonglong2 xb = *reinterpret_cast<const ulonglong2*>(xp + k * XSR + 4);
        float4 wf = *reinterpret_cast<const float4*>(wq + k * D);
        ull w0, w1, w2, w3;
        asm("mov.b64 %0, {%1, %1};" : "=l"(w0) : "f"(wf.x));
        asm("mov.b64 %0, {%1, %1};" : "=l"(w1) : "f"(wf.y));
        asm("mov.b64 %0, {%1, %1};" : "=l"(w2) : "f"(wf.z));
        asm("mov.b64 %0, {%1, %1};" : "=l"(w3) : "f"(wf.w));
        asm("fma.rn.f32x2 %0, %1, %2, %0;" : "+l"(acc[0][0]) : "l"(xa.x), "l"(w0));
        asm("fma.rn.f32x2 %0, %1, %2, %0;" : "+l"(acc[0][1]) : "l"(xa.x), "l"(w1));
        asm("fma.rn.f32x2 %0, %1, %2, %0;" : "+l"(acc[0][2]) : "l"(xa.x), "l"(w2));
        asm("fma.rn.f32x2 %0, %1, %2, %0;" : "+l"(acc[0][3]) : "l"(xa.x), "l"(w3));
        asm("fma.rn.f32x2 %0, %1, %2, %0;" : "+l"(acc[1][0]) : "l"(xa.y), "l"(w0));
        asm("fma.rn.f32x2 %0, %1, %2, %0;" : "+l"(acc[1][1]) : "l"(xa.y), "l"(w1));
        asm("fma.rn.f32x2 %0, %1, %2, %0;" : "+l"(acc[1][2]) : "l"(xa.y), "l"(w2));
        asm("fma.rn.f32x2 %0, %1, %2, %0;" : "+l"(acc[1][3]) : "l"(xa.y), "l"(w3));
        asm("fma.rn.f32x2 %0, %1, %2, %0;" : "+l"(acc[2][0]) : "l"(xb.x), "l"(w0));
        asm("fma.rn.f32x2 %0, %1, %2, %0;" : "+l"(acc[2][1]) : "l"(xb.x), "l"(w1));
        asm("fma.rn.f32x2 %0, %1, %2, %0;" : "+l"(acc[2][2]) : "l"(xb.x), "l"(w2));
        asm("fma.rn.f32x2 %0, %1, %2, %0;" : "+l"(acc[2][3]) : "l"(xb.x), "l"(w3));
        asm("fma.rn.f32x2 %0, %1, %2, %0;" : "+l"(acc[3][0]) : "l"(xb.y), "l"(w0));
        asm("fma.rn.f32x2 %0, %1, %2, %0;" : "+l"(acc[3][1]) : "l"(xb.y), "l"(w1));
        asm("fma.rn.f32x2 %0, %1, %2, %0;" : "+l"(acc[3][2]) : "l"(xb.y), "l"(w2));
        asm("fma.rn.f32x2 %0, %1, %2, %0;" : "+l"(acc[3][3]) : "l"(xb.y), "l"(w3));
    }

    // epilogue: unpack row-pairs, relu, store fp32 (+bf16 for stages 0,1)
#pragma unroll
    for (int m = 0; m < 4; m++) {
        float lo[4], hi[4];
#pragma unroll
        for (int c = 0; c < 4; c++)
            asm("mov.b64 {%0, %1}, %2;" : "=f"(lo[c]), "=f"(hi[c]) : "l"(acc[m][c]));
        int row0 = r0 + 8 * rg + 2 * m;
#pragma unroll
        for (int h = 0; h < 2; h++) {
            int grow = row0 + h;
            if (grow < n) {
                float4 o;
                o.x = fmaxf(h ? hi[0] : lo[0], 0.f);
                o.y = fmaxf(h ? hi[1] : lo[1], 0.f);
                o.z = fmaxf(h ? hi[2] : lo[2], 0.f);
                o.w = fmaxf(h ? hi[3] : lo[3], 0.f);
                *reinterpret_cast<float4*>(out + (size_t)grow * D + cg * 4) = o;
                if (stage != 2) {
                    __nv_bfloat162 h0 = __floats2bfloat162_rn(o.x, o.y);
                    __nv_bfloat162 h1 = __floats2bfloat162_rn(o.z, o.w);
                    uint2 hb;
                    hb.x = *reinterpret_cast<unsigned*>(&h0);
                    hb.y = *reinterpret_cast<unsigned*>(&h1);
                    *reinterpret_cast<uint2*>(g_zh + (size_t)grow * D + cg * 4) = hb;
                }
            }
        }
    }
}

// ---------------------------------------------------------------------------
extern "C" void kernel_launch(void* const* d_in, const int* in_sizes, int n_in,
                              void* d_out, int out_size) {
    // Bind inputs by element count (robust to ordering), positional fallback.
    int ix = -1, ie = -1, iW[3] = {-1, -1, -1}, ib[3] = {-1, -1, -1};
    int nW = 0, nb = 0;
    for (int i = 0; i < n_in; i++) {
        int s = in_sizes[i];
        if (s == N_NODES * D)          ix = i;
        else if (s == 2 * N_EDGES)     ie = i;
        else if (s == D * D && nW < 3) iW[nW++] = i;
        else if (s == D && nb < 3)     ib[nb++] = i;
    }
    if (ix < 0 || ie < 0 || nW < 3 || nb < 3) {
        ix = 0; ie = 1;
        iW[0] = 2; ib[0] = 3; iW[1] = 4; ib[1] = 5; iW[2] = 6; ib[2] = 7;
    }

    const float* x  = (const float*)d_in[ix];
    const void*  ei = d_in[ie];
    const float* W1 = (const float*)d_in[iW[0]];
    const float* b1 = (const float*)d_in[ib[0]];
    const float* W2 = (const float*)d_in[iW[1]];
    const float* b2 = (const float*)d_in[ib[1]];
    const float* W3 = (const float*)d_in[iW[2]];
    const float* b3 = (const float*)d_in[ib[2]];
    float* out = (float*)d_out;

    const int n = in_sizes[ix] / D;      // 100000
    const int E = in_sizes[ie] / 2;      // 1200000

    const int gemm_blocks   = (n + GR - 1) / GR;
    const int filter_blocks = (n * 16 + 255) / 256;
    const int node_blocks   = (n + 255) / 256;

    // graph prep: dtype probe, degree counts
    detect_dtype_kernel<<<1, 32>>>((const long long*)ei);
    init_counts_kernel<<<node_blocks, 256>>>(n);
    edge_prep_kernel<<<(E + 255) / 256, 256>>>(ei, E, n);

    // layer 1: x -> g_zA (+ bf16 copy)
    gemm_relu_kernel<<<gemm_blocks, 256>>>(x, nullptr, W1, b1, n, 0);

    // CSC build: parallel scan + bucket
    scan_partial_kernel<<<node_blocks, 256>>>(n);
    scan_bases_kernel<<<1, NBMAX>>>(node_blocks);
    scan_fill_kernel<<<node_blocks, 256>>>(n);
    bucket_kernel<<<(E + 255) / 256, 256>>>(ei, E, n);

    // filter 1: bf16 gather + fp32 own-row -> g_zf
    filter_kernel<<<filter_blocks, 256>>>(n, 0);

    // layer 2: g_zf -> g_zB (+ bf16 copy)
    gemm_relu_kernel<<<gemm_blocks, 256>>>(nullptr, nullptr, W2, b2, n, 1);

    // filter 2
    filter_kernel<<<filter_blocks, 256>>>(n, 1);

    // layer 3: g_zf -> d_out
    gemm_relu_kernel<<<gemm_blocks, 256>>>(nullptr, out, W3, b3, n, 2);
}